// round 4
// baseline (speedup 1.0000x reference)
#include <cuda_runtime.h>
#include <cstdint>

// Problem constants (shapes are fixed by the dataset)
#define FD    128
#define MAXN  50000
#define MAXE  625000

// ---------------- scratch (no allocation allowed -> device globals) ----------
__device__ __align__(128) float g_y[MAXN * FD];     // y = (A@W) * dinv[row]
__device__ __align__(128) float g_agg[MAXN * FD];   // aggregation buffer
__device__ float g_deg[MAXN];
__device__ float g_dinv[MAXN];
__device__ int   g_src[MAXE];
__device__ int   g_dst[MAXE];
__device__ int   g_is64;

// ---------------- dtype detection: int64 vs int32 edge_index -----------------
// If the buffer holds int64 little-endian values < 2^31, every odd 32-bit word
// is zero. If it holds int32 random indices in [0, 50000), odd words are
// nonzero with overwhelming probability.
__global__ void detect_kernel(const int* __restrict__ e) {
    int lane = threadIdx.x;
    int nz = 0;
    for (int i = lane; i < 128; i += 32) nz |= (e[2 * i + 1] != 0);
    nz = __any_sync(0xffffffffu, nz);
    if (lane == 0) g_is64 = nz ? 0 : 1;
}

// Convert edge_index to int32 src/dst arrays; also init deg = 1 (self-loop).
__global__ void convert_kernel(const int* __restrict__ e, int E, int n) {
    const int is64 = g_is64;
    const int stride = gridDim.x * blockDim.x;
    for (int i = blockIdx.x * blockDim.x + threadIdx.x; i < E; i += stride) {
        if (is64) {
            g_src[i] = e[2 * i];
            g_dst[i] = e[2 * (E + i)];
        } else {
            g_src[i] = e[i];
            g_dst[i] = e[E + i];
        }
    }
    for (int i = blockIdx.x * blockDim.x + threadIdx.x; i < n; i += stride) {
        g_deg[i] = 1.0f;
    }
}

__global__ void deg_kernel(int E) {
    const int stride = gridDim.x * blockDim.x;
    for (int i = blockIdx.x * blockDim.x + threadIdx.x; i < E; i += stride) {
        atomicAdd(&g_deg[g_dst[i]], 1.0f);
    }
}

__global__ void dinv_kernel(int n) {
    int i = blockIdx.x * blockDim.x + threadIdx.x;
    if (i < n) g_dinv[i] = rsqrtf(g_deg[i]);  // deg >= 1 always (self-loop)
}

// ---------------- GEMM: y = transform(A) @ W * dinv[row]; agg = y ------------
// LAYER==1: A = x (raw input).
// LAYER==2: A[row][k] = relu(dinv[row] * g_agg[row][k] + bprev[k]) on the fly.
//           In-place safe: each block only reads/writes its own 64 rows, and
//           all reads complete before the epilogue writes.
template <int LAYER>
__global__ void __launch_bounds__(256)
gemm_kernel(const float* __restrict__ A, const float* __restrict__ W,
            const float* __restrict__ bprev, int n) {
    __shared__ float As[64][33];     // +1 pad to avoid bank conflicts
    __shared__ float Ws[32][FD];

    const int row0 = blockIdx.x * 64;
    const int tid = threadIdx.x;
    const int tx = tid & 15;   // 16 col-groups of 8
    const int ty = tid >> 4;   // 16 row-groups of 4

    float acc[4][8];
#pragma unroll
    for (int i = 0; i < 4; i++)
#pragma unroll
        for (int j = 0; j < 8; j++) acc[i][j] = 0.0f;

    for (int k0 = 0; k0 < FD; k0 += 32) {
        // stage A tile: 64 rows x 32 k, as 512 float4 (2 per thread)
#pragma unroll
        for (int t = 0; t < 2; t++) {
            int i = tid + t * 256;
            int r = i >> 3;
            int c4 = i & 7;
            int row = row0 + r;
            float4 v = make_float4(0.f, 0.f, 0.f, 0.f);
            if (row < n) {
                if (LAYER == 1) {
                    v = *reinterpret_cast<const float4*>(&A[(size_t)row * FD + k0 + c4 * 4]);
                } else {
                    v = *reinterpret_cast<const float4*>(&g_agg[(size_t)row * FD + k0 + c4 * 4]);
                    float di = g_dinv[row];
                    float4 bb = *reinterpret_cast<const float4*>(&bprev[k0 + c4 * 4]);
                    v.x = fmaxf(fmaf(di, v.x, bb.x), 0.f);
                    v.y = fmaxf(fmaf(di, v.y, bb.y), 0.f);
                    v.z = fmaxf(fmaf(di, v.z, bb.z), 0.f);
                    v.w = fmaxf(fmaf(di, v.w, bb.w), 0.f);
                }
            }
            As[r][c4 * 4 + 0] = v.x;
            As[r][c4 * 4 + 1] = v.y;
            As[r][c4 * 4 + 2] = v.z;
            As[r][c4 * 4 + 3] = v.w;
        }
        // stage W tile: 32 k x 128 n, as 1024 float4 (4 per thread)
#pragma unroll
        for (int t = 0; t < 4; t++) {
            int i = tid + t * 256;
            int kk = i >> 5;
            int c4 = i & 31;
            *reinterpret_cast<float4*>(&Ws[kk][c4 * 4]) =
                *reinterpret_cast<const float4*>(&W[(size_t)(k0 + kk) * FD + c4 * 4]);
        }
        __syncthreads();

#pragma unroll
        for (int kk = 0; kk < 32; kk++) {
            float a[4];
#pragma unroll
            for (int i = 0; i < 4; i++) a[i] = As[ty * 4 + i][kk];
            float w[8];
            *reinterpret_cast<float4*>(&w[0]) = *reinterpret_cast<const float4*>(&Ws[kk][tx * 8]);
            *reinterpret_cast<float4*>(&w[4]) = *reinterpret_cast<const float4*>(&Ws[kk][tx * 8 + 4]);
#pragma unroll
            for (int i = 0; i < 4; i++)
#pragma unroll
                for (int j = 0; j < 8; j++) acc[i][j] = fmaf(a[i], w[j], acc[i][j]);
        }
        __syncthreads();
    }

    // epilogue: y = acc * dinv[row]; agg = y (self-loop contribution)
#pragma unroll
    for (int i = 0; i < 4; i++) {
        int row = row0 + ty * 4 + i;
        if (row >= n) continue;
        float di = g_dinv[row];
        float4 o0 = make_float4(acc[i][0] * di, acc[i][1] * di, acc[i][2] * di, acc[i][3] * di);
        float4 o1 = make_float4(acc[i][4] * di, acc[i][5] * di, acc[i][6] * di, acc[i][7] * di);
        size_t base = (size_t)row * FD + tx * 8;
        *reinterpret_cast<float4*>(&g_y[base])       = o0;
        *reinterpret_cast<float4*>(&g_y[base + 4])   = o1;
        *reinterpret_cast<float4*>(&g_agg[base])     = o0;
        *reinterpret_cast<float4*>(&g_agg[base + 4]) = o1;
    }
}

// ---------------- edge scatter: agg[dst] += y[src], one warp per edge --------
__global__ void __launch_bounds__(256) scatter_kernel(int E) {
    int gwarp = (blockIdx.x * blockDim.x + threadIdx.x) >> 5;
    int lane = threadIdx.x & 31;
    if (gwarp >= E) return;
    int sd = 0;
    if (lane < 2) sd = lane ? g_dst[gwarp] : g_src[gwarp];
    int s = __shfl_sync(0xffffffffu, sd, 0);
    int d = __shfl_sync(0xffffffffu, sd, 1);
    float4 v = *reinterpret_cast<const float4*>(&g_y[(size_t)s * FD + lane * 4]);
    float* p = &g_agg[(size_t)d * FD + lane * 4];
    // vectorized no-return reduction (sm_90+): 1 L2 op per 16B
    asm volatile("red.global.add.v4.f32 [%0], {%1,%2,%3,%4};"
                 :: "l"(p), "f"(v.x), "f"(v.y), "f"(v.z), "f"(v.w)
                 : "memory");
}

// ---------------- final epilogue: out = relu(dinv*agg + b2) ------------------
__global__ void final_kernel(const float* __restrict__ b2, float* __restrict__ out, int n) {
    int total4 = n * (FD / 4);
    for (int i = blockIdx.x * blockDim.x + threadIdx.x; i < total4;
         i += gridDim.x * blockDim.x) {
        int row = i >> 5;        // FD/4 = 32 float4 per row
        int c4 = i & 31;
        float di = g_dinv[row];
        float4 a = *reinterpret_cast<const float4*>(&g_agg[(size_t)i * 4]);
        float4 bb = *reinterpret_cast<const float4*>(&b2[c4 * 4]);
        float4 r;
        r.x = fmaxf(fmaf(di, a.x, bb.x), 0.f);
        r.y = fmaxf(fmaf(di, a.y, bb.y), 0.f);
        r.z = fmaxf(fmaf(di, a.z, bb.z), 0.f);
        r.w = fmaxf(fmaf(di, a.w, bb.w), 0.f);
        *reinterpret_cast<float4*>(&out[(size_t)i * 4]) = r;
    }
}

extern "C" void kernel_launch(void* const* d_in, const int* in_sizes, int n_in,
                              void* d_out, int out_size) {
    const float* x  = (const float*)d_in[0];
    const int*   e  = (const int*)d_in[1];   // int32 or int64 (detected on-device)
    const float* W1 = (const float*)d_in[2];
    const float* b1 = (const float*)d_in[3];
    const float* W2 = (const float*)d_in[4];
    const float* b2 = (const float*)d_in[5];
    float* out = (float*)d_out;

    const int n = in_sizes[0] / FD;   // 50000
    const int E = in_sizes[1] / 2;    // 625000 (element count independent of dtype)

    detect_kernel<<<1, 32>>>(e);
    convert_kernel<<<(E + 255) / 256, 256>>>(e, E, n);
    deg_kernel<<<(E + 255) / 256, 256>>>(E);
    dinv_kernel<<<(n + 255) / 256, 256>>>(n);

    const int gblocks = (n + 63) / 64;
    const int sblocks = (E + 7) / 8;          // 8 warps (edges) per block
    const int fblocks = (n * (FD / 4) + 255) / 256;

    // layer 1
    gemm_kernel<1><<<gblocks, 256>>>(x, W1, nullptr, n);
    scatter_kernel<<<sblocks, 256>>>(E);
    // layer 2 (folds relu(dinv*agg1 + b1) into its A-load)
    gemm_kernel<2><<<gblocks, 256>>>(x, W2, b1, n);
    scatter_kernel<<<sblocks, 256>>>(E);
    // out = relu(dinv*agg2 + b2)
    final_kernel<<<fblocks, 256>>>(b2, out, n);
}